// round 6
// baseline (speedup 1.0000x reference)
#include <cuda_runtime.h>
#include <cuda_fp16.h>
#include <math.h>

#define NN 100000
#define EE 1600000
#define ETOT (EE + NN)
#define DIM 128
#define HID 16
#define HEADS 4
#define F1 (HEADS * HID)   // 64
#define NEG 0.2f

#define SCAN_BLK 512
#define NBLK ((NN + SCAN_BLK - 1) / SCAN_BLK)   // 196

// ---------------- scratch (static device globals; no allocation) -------------
__device__ __align__(16) __half g_h1h[NN * F1];   // layer-1 features (fp16)
__device__ __align__(16) float g_as1[NN * HEADS];
__device__ __align__(16) float g_ad1[NN * HEADS];
__device__ __align__(16) float g_h3[NN * 2];      // layer-2 transformed features
__device__ float g_as2[NN];
__device__ float g_ad2[NN];

__device__ int g_deg[NN];
__device__ int g_offs[NN];
__device__ int g_cur[NN];
__device__ int g_bsum[256];
__device__ int g_bpre[256];
__device__ int g_csr_src[ETOT];

// ---------------- helpers ----------------------------------------------------
__device__ __forceinline__ float lrelu(float v) {
    return v > 0.0f ? v : NEG * v;
}

// ---------------- kernels ----------------------------------------------------

__global__ void k_init() {
    int i = blockIdx.x * blockDim.x + threadIdx.x;
    if (i < NN) g_deg[i] = 0;
}

// h1 = x @ W1 (fp32 math, fp16 store); alpha_s1/alpha_d1 per (node, head)
__global__ __launch_bounds__(256) void k_gemm1(
    const float* __restrict__ x, const float* __restrict__ W1,
    const float* __restrict__ asrc, const float* __restrict__ adst) {

    __shared__ float4 Ws[DIM * F1 / 4];   // 32KB
    int tid = threadIdx.x;
    #pragma unroll
    for (int i = tid; i < DIM * F1 / 4; i += 256)
        Ws[i] = ((const float4*)W1)[i];
    __syncthreads();

    int nodeLocal = tid >> 3;     // 0..31
    int tj = tid & 7;             // channels [tj*8, tj*8+8)
    int n = blockIdx.x * 32 + nodeLocal;
    const float* xr = x + (size_t)n * DIM;

    float4 a0 = make_float4(0.f, 0.f, 0.f, 0.f);
    float4 a1 = make_float4(0.f, 0.f, 0.f, 0.f);
    #pragma unroll 4
    for (int k = 0; k < DIM; k++) {
        float xv = __ldg(xr + k);
        float4 w0 = Ws[k * 16 + tj * 2];
        float4 w1 = Ws[k * 16 + tj * 2 + 1];
        a0.x += xv * w0.x; a0.y += xv * w0.y; a0.z += xv * w0.z; a0.w += xv * w0.w;
        a1.x += xv * w1.x; a1.y += xv * w1.y; a1.z += xv * w1.z; a1.w += xv * w1.w;
    }

    // fp16 store: 8 channels -> 4 half2 = 16B
    union { __half2 h2[4]; uint4 u; } pk;
    pk.h2[0] = __floats2half2_rn(a0.x, a0.y);
    pk.h2[1] = __floats2half2_rn(a0.z, a0.w);
    pk.h2[2] = __floats2half2_rn(a1.x, a1.y);
    pk.h2[3] = __floats2half2_rn(a1.z, a1.w);
    *(uint4*)(g_h1h + (size_t)n * F1 + tj * 8) = pk.u;

    int j0 = tj * 8;
    float ps = a0.x * asrc[j0]     + a0.y * asrc[j0 + 1] +
               a0.z * asrc[j0 + 2] + a0.w * asrc[j0 + 3] +
               a1.x * asrc[j0 + 4] + a1.y * asrc[j0 + 5] +
               a1.z * asrc[j0 + 6] + a1.w * asrc[j0 + 7];
    float pd = a0.x * adst[j0]     + a0.y * adst[j0 + 1] +
               a0.z * adst[j0 + 2] + a0.w * adst[j0 + 3] +
               a1.x * adst[j0 + 4] + a1.y * adst[j0 + 5] +
               a1.z * adst[j0 + 6] + a1.w * adst[j0 + 7];
    ps += __shfl_xor_sync(0xffffffffu, ps, 1);
    pd += __shfl_xor_sync(0xffffffffu, pd, 1);
    if ((tj & 1) == 0) {
        int h = tj >> 1;
        g_as1[n * HEADS + h] = ps;
        g_ad1[n * HEADS + h] = pd;
    }
}

// ---------------- CSR build ---------------------------------------------------
__global__ void k_count(const int* __restrict__ ei) {
    int t = blockIdx.x * blockDim.x + threadIdx.x;
    if (t >= ETOT / 4) return;
    int e = t * 4;
    if (e < EE) {
        int4 d4 = *(const int4*)(ei + EE + e);
        atomicAdd(&g_deg[d4.x], 1);
        atomicAdd(&g_deg[d4.y], 1);
        atomicAdd(&g_deg[d4.z], 1);
        atomicAdd(&g_deg[d4.w], 1);
    } else {
        int n = e - EE;
        atomicAdd(&g_deg[n + 0], 1);
        atomicAdd(&g_deg[n + 1], 1);
        atomicAdd(&g_deg[n + 2], 1);
        atomicAdd(&g_deg[n + 3], 1);
    }
}

__global__ __launch_bounds__(SCAN_BLK) void k_scan1() {
    __shared__ int sh[SCAN_BLK];
    int t = threadIdx.x;
    int i = blockIdx.x * SCAN_BLK + t;
    int v = (i < NN) ? g_deg[i] : 0;
    sh[t] = v;
    __syncthreads();
    #pragma unroll
    for (int off = 1; off < SCAN_BLK; off <<= 1) {
        int add = (t >= off) ? sh[t - off] : 0;
        __syncthreads();
        sh[t] += add;
        __syncthreads();
    }
    if (i < NN) g_offs[i] = sh[t] - v;   // exclusive
    if (t == SCAN_BLK - 1) g_bsum[blockIdx.x] = sh[t];
}

__global__ __launch_bounds__(256) void k_scan2() {
    __shared__ int sh[256];
    int t = threadIdx.x;
    int v = (t < NBLK) ? g_bsum[t] : 0;
    sh[t] = v;
    __syncthreads();
    #pragma unroll
    for (int off = 1; off < 256; off <<= 1) {
        int add = (t >= off) ? sh[t - off] : 0;
        __syncthreads();
        sh[t] += add;
        __syncthreads();
    }
    if (t < NBLK) g_bpre[t] = sh[t] - v;  // exclusive
}

__global__ void k_scan3() {
    int i = blockIdx.x * blockDim.x + threadIdx.x;
    if (i >= NN) return;
    int o = g_offs[i] + g_bpre[i / SCAN_BLK];
    g_offs[i] = o;
    g_cur[i] = o;
}

__global__ void k_scatter(const int* __restrict__ ei) {
    int t = blockIdx.x * blockDim.x + threadIdx.x;
    if (t >= ETOT / 4) return;
    int e = t * 4;
    int s[4], d[4];
    if (e < EE) {
        int4 s4 = *(const int4*)(ei + e);
        int4 d4 = *(const int4*)(ei + EE + e);
        s[0] = s4.x; s[1] = s4.y; s[2] = s4.z; s[3] = s4.w;
        d[0] = d4.x; d[1] = d4.y; d[2] = d4.z; d[3] = d4.w;
    } else {
        int n = e - EE;
        #pragma unroll
        for (int j = 0; j < 4; j++) { s[j] = n + j; d[j] = n + j; }
    }
    #pragma unroll
    for (int j = 0; j < 4; j++) {
        int pos = atomicAdd(&g_cur[d[j]], 1);
        g_csr_src[pos] = s[j];
    }
}

// ---------------- layer-1 aggregation (atomic-free) + fused l2prep ------------
// One warp per dst node. Lane owns channels (2*lane, 2*lane+1); head = lane>>3.
__global__ __launch_bounds__(256) void k_agg1(
    const float* __restrict__ b1, const float* __restrict__ W2,
    const float* __restrict__ as2, const float* __restrict__ ad2) {

    int lane = threadIdx.x & 31;
    int n = blockIdx.x * 8 + (threadIdx.x >> 5);
    if (n >= NN) return;

    int h = lane >> 3;
    float adh = g_ad1[n * 4 + h];
    int start = g_offs[n];
    int end = start + g_deg[n];
    int c = 2 * lane;

    float acc0 = 0.f, acc1 = 0.f, wsum = 0.f;
    int i = start;
    for (; i + 4 <= end; i += 4) {
        int s0 = __ldg(g_csr_src + i + 0);
        int s1 = __ldg(g_csr_src + i + 1);
        int s2 = __ldg(g_csr_src + i + 2);
        int s3 = __ldg(g_csr_src + i + 3);
        float e0 = __ldg(g_as1 + s0 * 4 + h);
        float e1 = __ldg(g_as1 + s1 * 4 + h);
        float e2 = __ldg(g_as1 + s2 * 4 + h);
        float e3 = __ldg(g_as1 + s3 * 4 + h);
        float2 q0 = __half22float2(*(const __half2*)(g_h1h + (size_t)s0 * F1 + c));
        float2 q1 = __half22float2(*(const __half2*)(g_h1h + (size_t)s1 * F1 + c));
        float2 q2 = __half22float2(*(const __half2*)(g_h1h + (size_t)s2 * F1 + c));
        float2 q3 = __half22float2(*(const __half2*)(g_h1h + (size_t)s3 * F1 + c));
        float w0 = __expf(lrelu(e0 + adh));
        float w1 = __expf(lrelu(e1 + adh));
        float w2 = __expf(lrelu(e2 + adh));
        float w3 = __expf(lrelu(e3 + adh));
        acc0 += w0 * q0.x + w1 * q1.x;
        acc1 += w0 * q0.y + w1 * q1.y;
        acc0 += w2 * q2.x + w3 * q3.x;
        acc1 += w2 * q2.y + w3 * q3.y;
        wsum += (w0 + w1) + (w2 + w3);
    }
    for (; i < end; i++) {
        int s = __ldg(g_csr_src + i);
        float as = __ldg(g_as1 + s * 4 + h);
        float w = __expf(lrelu(as + adh));
        float2 hv = __half22float2(*(const __half2*)(g_h1h + (size_t)s * F1 + c));
        acc0 += w * hv.x;
        acc1 += w * hv.y;
        wsum += w;
    }

    float inv = 1.0f / (wsum + 1e-16f);
    int c0 = c, c1 = c + 1;
    float v0 = acc0 * inv + b1[c0];
    float v1 = acc1 * inv + b1[c1];
    v0 = v0 > 0.f ? v0 : expm1f(v0);          // ELU
    v1 = v1 > 0.f ? v1 : expm1f(v1);

    float p0 = v0 * W2[c0 * 2 + 0] + v1 * W2[c1 * 2 + 0];
    float p1 = v0 * W2[c0 * 2 + 1] + v1 * W2[c1 * 2 + 1];
    #pragma unroll
    for (int o = 16; o > 0; o >>= 1) {
        p0 += __shfl_down_sync(0xffffffffu, p0, o);
        p1 += __shfl_down_sync(0xffffffffu, p1, o);
    }
    if (lane == 0) {
        g_h3[n * 2 + 0] = p0;
        g_h3[n * 2 + 1] = p1;
        g_as2[n] = p0 * as2[0] + p1 * as2[1];
        g_ad2[n] = p0 * ad2[0] + p1 * ad2[1];
    }
}

// ---------------- layer-2 aggregation (atomic-free) + output ------------------
__global__ __launch_bounds__(256) void k_agg2(
    float* __restrict__ out, const float* __restrict__ b2) {

    int lane = threadIdx.x & 31;
    int n = blockIdx.x * 8 + (threadIdx.x >> 5);
    if (n >= NN) return;

    float ad = g_ad2[n];
    int start = g_offs[n];
    int end = start + g_deg[n];

    float a0 = 0.f, a1 = 0.f, wsum = 0.f;
    for (int i = start + lane; i < end; i += 32) {
        int s = __ldg(g_csr_src + i);
        float w = __expf(lrelu(__ldg(g_as2 + s) + ad));
        float2 hv = *(const float2*)(g_h3 + s * 2);
        a0 += w * hv.x;
        a1 += w * hv.y;
        wsum += w;
    }
    #pragma unroll
    for (int o = 16; o > 0; o >>= 1) {
        a0   += __shfl_down_sync(0xffffffffu, a0, o);
        a1   += __shfl_down_sync(0xffffffffu, a1, o);
        wsum += __shfl_down_sync(0xffffffffu, wsum, o);
    }
    if (lane == 0) {
        float inv = 1.0f / (wsum + 1e-16f);
        out[n * 2 + 0] = a0 * inv + b2[0];
        out[n * 2 + 1] = a1 * inv + b2[1];
    }
}

// ---------------- launch ------------------------------------------------------
extern "C" void kernel_launch(void* const* d_in, const int* in_sizes, int n_in,
                              void* d_out, int out_size) {
    const float* x    = (const float*)d_in[0];
    const int*   ei   = (const int*)  d_in[1];
    const float* W1   = (const float*)d_in[2];
    const float* as1  = (const float*)d_in[3];
    const float* ad1  = (const float*)d_in[4];
    const float* b1   = (const float*)d_in[5];
    const float* W2   = (const float*)d_in[6];
    const float* as2  = (const float*)d_in[7];
    const float* ad2  = (const float*)d_in[8];
    const float* b2   = (const float*)d_in[9];
    float* out = (float*)d_out;

    // One-time host-side resources (host objects only; no device allocation).
    static cudaStream_t s2 = nullptr;
    static cudaEvent_t evFork = nullptr, evJoin = nullptr;
    if (!s2) {
        cudaStreamCreateWithFlags(&s2, cudaStreamNonBlocking);
        cudaEventCreateWithFlags(&evFork, cudaEventDisableTiming);
        cudaEventCreateWithFlags(&evJoin, cudaEventDisableTiming);
    }

    const int T = 256;

    // Fork: CSR build chain (depends only on ei) on s2, concurrent with GEMM.
    cudaEventRecord(evFork, 0);
    cudaStreamWaitEvent(s2, evFork, 0);

    k_init<<<(NN + T - 1) / T, T, 0, s2>>>();
    k_count<<<(ETOT / 4 + T - 1) / T, T, 0, s2>>>(ei);
    k_scan1<<<NBLK, SCAN_BLK, 0, s2>>>();

    k_gemm1<<<NN / 32, T>>>(x, W1, as1, ad1);          // main stream (4th launch)

    k_scan2<<<1, 256, 0, s2>>>();
    k_scan3<<<(NN + T - 1) / T, T, 0, s2>>>();
    k_scatter<<<(ETOT / 4 + T - 1) / T, T, 0, s2>>>(ei);

    // Join
    cudaEventRecord(evJoin, s2);
    cudaStreamWaitEvent(0, evJoin, 0);

    k_agg1<<<(NN + 7) / 8, T>>>(b1, W2, as2, ad2);
    k_agg2<<<(NN + 7) / 8, T>>>(out, b2);
}

// round 7
// speedup vs baseline: 1.9412x; 1.9412x over previous
#include <cuda_runtime.h>
#include <cuda_fp16.h>
#include <math.h>

#define NN 100000
#define EE 1600000
#define ETOT (EE + NN)
#define DIM 128
#define HID 16
#define HEADS 4
#define F1 (HEADS * HID)   // 64
#define NEG 0.2f

#define SCAN_BLK 512
#define NBLK ((NN + SCAN_BLK - 1) / SCAN_BLK)   // 196

// gemm tiling
#define GNODES 128
#define XS_PITCH 129
#define GEMM_SMEM ((GNODES * XS_PITCH + DIM * F1) * 4)   // 98816 bytes

// ---------------- scratch (static device globals; no allocation) -------------
__device__ __align__(16) __half g_h1h[NN * F1];   // layer-1 features (fp16)
__device__ __align__(16) float g_as1[NN * HEADS];
__device__ __align__(16) float g_ad1[NN * HEADS];
__device__ __align__(16) float g_h3[NN * 2];      // layer-2 transformed features
__device__ float g_as2[NN];
__device__ float g_ad2[NN];

__device__ int g_deg[NN];
__device__ int g_offs[NN];
__device__ int g_cur[NN];
__device__ int g_bsum[256];
__device__ int g_bpre[256];
__device__ int g_csr_src[ETOT];

// ---------------- helpers ----------------------------------------------------
__device__ __forceinline__ float lrelu(float v) {
    return v > 0.0f ? v : NEG * v;
}

// ---------------- kernels ----------------------------------------------------

__global__ void k_init() {
    int i = blockIdx.x * blockDim.x + threadIdx.x;
    if (i < NN) g_deg[i] = 0;
}

// h1 = x @ W1 (register-tiled: 4 nodes x 8 channels per thread).
// fp32 math, fp16 store; alpha_s1/alpha_d1 per (node, head).
__global__ __launch_bounds__(256, 2) void k_gemm1(
    const float* __restrict__ x, const float* __restrict__ W1,
    const float* __restrict__ asrc, const float* __restrict__ adst) {

    extern __shared__ float sm[];
    float* xs = sm;                        // [GNODES][XS_PITCH]
    float* Ws = sm + GNODES * XS_PITCH;    // [DIM][F1] row-major

    int tid = threadIdx.x;
    int n0 = blockIdx.x * GNODES;

    // load W (contiguous float4 copy)
    #pragma unroll
    for (int i = tid; i < DIM * F1 / 4; i += 256)
        ((float4*)Ws)[i] = ((const float4*)W1)[i];

    // load x tile: 128 rows x 32 float4, coalesced; pitch-129 scalar stores
    for (int i = tid; i < GNODES * 32; i += 256) {
        int r = i >> 5, c4 = i & 31;
        float4 v = (n0 + r < NN)
                 ? ((const float4*)(x + (size_t)(n0 + r) * DIM))[c4]
                 : make_float4(0.f, 0.f, 0.f, 0.f);
        float* dp = xs + r * XS_PITCH + c4 * 4;
        dp[0] = v.x; dp[1] = v.y; dp[2] = v.z; dp[3] = v.w;
    }
    __syncthreads();

    int ct = tid & 7;     // channel group: channels [ct*8, ct*8+8)
    int nt = tid >> 3;    // node group: nodes nt*4 .. nt*4+3 (local)

    // attention vectors for this thread's 8 channels (registers)
    float ar[8], dr[8];
    #pragma unroll
    for (int i = 0; i < 8; i++) {
        ar[i] = __ldg(asrc + ct * 8 + i);
        dr[i] = __ldg(adst + ct * 8 + i);
    }

    float acc[4][8];
    #pragma unroll
    for (int j = 0; j < 4; j++)
        #pragma unroll
        for (int i = 0; i < 8; i++) acc[j][i] = 0.f;

    #pragma unroll 2
    for (int k = 0; k < DIM; k++) {
        float4 w0 = *(const float4*)(Ws + k * F1 + ct * 8);
        float4 w1 = *(const float4*)(Ws + k * F1 + ct * 8 + 4);
        float xv[4];
        #pragma unroll
        for (int j = 0; j < 4; j++)
            xv[j] = xs[(nt * 4 + j) * XS_PITCH + k];
        #pragma unroll
        for (int j = 0; j < 4; j++) {
            acc[j][0] += xv[j] * w0.x;
            acc[j][1] += xv[j] * w0.y;
            acc[j][2] += xv[j] * w0.z;
            acc[j][3] += xv[j] * w0.w;
            acc[j][4] += xv[j] * w1.x;
            acc[j][5] += xv[j] * w1.y;
            acc[j][6] += xv[j] * w1.z;
            acc[j][7] += xv[j] * w1.w;
        }
    }

    // epilogue: fp16 store + per-head logits (heads span 16 ch = 2 ct groups)
    #pragma unroll
    for (int j = 0; j < 4; j++) {
        int n = n0 + nt * 4 + j;
        float ps = 0.f, pd = 0.f;
        #pragma unroll
        for (int i = 0; i < 8; i++) {
            ps += acc[j][i] * ar[i];
            pd += acc[j][i] * dr[i];
        }
        // combine the two ct-groups of each head (lane xor 1 flips ct bit0)
        ps += __shfl_xor_sync(0xffffffffu, ps, 1);
        pd += __shfl_xor_sync(0xffffffffu, pd, 1);

        if (n < NN) {
            union { __half2 h2[4]; uint4 u; } pk;
            pk.h2[0] = __floats2half2_rn(acc[j][0], acc[j][1]);
            pk.h2[1] = __floats2half2_rn(acc[j][2], acc[j][3]);
            pk.h2[2] = __floats2half2_rn(acc[j][4], acc[j][5]);
            pk.h2[3] = __floats2half2_rn(acc[j][6], acc[j][7]);
            *(uint4*)(g_h1h + (size_t)n * F1 + ct * 8) = pk.u;
            if ((ct & 1) == 0) {
                int h = ct >> 1;
                g_as1[n * HEADS + h] = ps;
                g_ad1[n * HEADS + h] = pd;
            }
        }
    }
}

// ---------------- CSR build ---------------------------------------------------
__global__ void k_count(const int* __restrict__ ei) {
    int t = blockIdx.x * blockDim.x + threadIdx.x;
    if (t >= ETOT / 4) return;
    int e = t * 4;
    if (e < EE) {
        int4 d4 = *(const int4*)(ei + EE + e);
        atomicAdd(&g_deg[d4.x], 1);
        atomicAdd(&g_deg[d4.y], 1);
        atomicAdd(&g_deg[d4.z], 1);
        atomicAdd(&g_deg[d4.w], 1);
    } else {
        int n = e - EE;
        atomicAdd(&g_deg[n + 0], 1);
        atomicAdd(&g_deg[n + 1], 1);
        atomicAdd(&g_deg[n + 2], 1);
        atomicAdd(&g_deg[n + 3], 1);
    }
}

__global__ __launch_bounds__(SCAN_BLK) void k_scan1() {
    __shared__ int sh[SCAN_BLK];
    int t = threadIdx.x;
    int i = blockIdx.x * SCAN_BLK + t;
    int v = (i < NN) ? g_deg[i] : 0;
    sh[t] = v;
    __syncthreads();
    #pragma unroll
    for (int off = 1; off < SCAN_BLK; off <<= 1) {
        int add = (t >= off) ? sh[t - off] : 0;
        __syncthreads();
        sh[t] += add;
        __syncthreads();
    }
    if (i < NN) g_offs[i] = sh[t] - v;   // exclusive
    if (t == SCAN_BLK - 1) g_bsum[blockIdx.x] = sh[t];
}

__global__ __launch_bounds__(256) void k_scan2() {
    __shared__ int sh[256];
    int t = threadIdx.x;
    int v = (t < NBLK) ? g_bsum[t] : 0;
    sh[t] = v;
    __syncthreads();
    #pragma unroll
    for (int off = 1; off < 256; off <<= 1) {
        int add = (t >= off) ? sh[t - off] : 0;
        __syncthreads();
        sh[t] += add;
        __syncthreads();
    }
    if (t < NBLK) g_bpre[t] = sh[t] - v;  // exclusive
}

__global__ void k_scan3() {
    int i = blockIdx.x * blockDim.x + threadIdx.x;
    if (i >= NN) return;
    int o = g_offs[i] + g_bpre[i / SCAN_BLK];
    g_offs[i] = o;
    g_cur[i] = o;
}

__global__ void k_scatter(const int* __restrict__ ei) {
    int t = blockIdx.x * blockDim.x + threadIdx.x;
    if (t >= ETOT / 4) return;
    int e = t * 4;
    int s[4], d[4];
    if (e < EE) {
        int4 s4 = *(const int4*)(ei + e);
        int4 d4 = *(const int4*)(ei + EE + e);
        s[0] = s4.x; s[1] = s4.y; s[2] = s4.z; s[3] = s4.w;
        d[0] = d4.x; d[1] = d4.y; d[2] = d4.z; d[3] = d4.w;
    } else {
        int n = e - EE;
        #pragma unroll
        for (int j = 0; j < 4; j++) { s[j] = n + j; d[j] = n + j; }
    }
    #pragma unroll
    for (int j = 0; j < 4; j++) {
        int pos = atomicAdd(&g_cur[d[j]], 1);
        g_csr_src[pos] = s[j];
    }
}

// ---------------- layer-1 aggregation (atomic-free) + fused l2prep ------------
// One warp per dst node. Lane owns channels (2*lane, 2*lane+1); head = lane>>3.
__global__ __launch_bounds__(256) void k_agg1(
    const float* __restrict__ b1, const float* __restrict__ W2,
    const float* __restrict__ as2, const float* __restrict__ ad2) {

    int lane = threadIdx.x & 31;
    int n = blockIdx.x * 8 + (threadIdx.x >> 5);
    if (n >= NN) return;

    int h = lane >> 3;
    float adh = g_ad1[n * 4 + h];
    int start = g_offs[n];
    int end = start + g_deg[n];
    int c = 2 * lane;

    float acc0 = 0.f, acc1 = 0.f, wsum = 0.f;
    int i = start;
    for (; i + 4 <= end; i += 4) {
        int s0 = __ldg(g_csr_src + i + 0);
        int s1 = __ldg(g_csr_src + i + 1);
        int s2 = __ldg(g_csr_src + i + 2);
        int s3 = __ldg(g_csr_src + i + 3);
        float e0 = __ldg(g_as1 + s0 * 4 + h);
        float e1 = __ldg(g_as1 + s1 * 4 + h);
        float e2 = __ldg(g_as1 + s2 * 4 + h);
        float e3 = __ldg(g_as1 + s3 * 4 + h);
        float2 q0 = __half22float2(*(const __half2*)(g_h1h + (size_t)s0 * F1 + c));
        float2 q1 = __half22float2(*(const __half2*)(g_h1h + (size_t)s1 * F1 + c));
        float2 q2 = __half22float2(*(const __half2*)(g_h1h + (size_t)s2 * F1 + c));
        float2 q3 = __half22float2(*(const __half2*)(g_h1h + (size_t)s3 * F1 + c));
        float w0 = __expf(lrelu(e0 + adh));
        float w1 = __expf(lrelu(e1 + adh));
        float w2 = __expf(lrelu(e2 + adh));
        float w3 = __expf(lrelu(e3 + adh));
        acc0 += w0 * q0.x + w1 * q1.x;
        acc1 += w0 * q0.y + w1 * q1.y;
        acc0 += w2 * q2.x + w3 * q3.x;
        acc1 += w2 * q2.y + w3 * q3.y;
        wsum += (w0 + w1) + (w2 + w3);
    }
    for (; i < end; i++) {
        int s = __ldg(g_csr_src + i);
        float as = __ldg(g_as1 + s * 4 + h);
        float w = __expf(lrelu(as + adh));
        float2 hv = __half22float2(*(const __half2*)(g_h1h + (size_t)s * F1 + c));
        acc0 += w * hv.x;
        acc1 += w * hv.y;
        wsum += w;
    }

    float inv = 1.0f / (wsum + 1e-16f);
    int c0 = c, c1 = c + 1;
    float v0 = acc0 * inv + b1[c0];
    float v1 = acc1 * inv + b1[c1];
    v0 = v0 > 0.f ? v0 : expm1f(v0);          // ELU
    v1 = v1 > 0.f ? v1 : expm1f(v1);

    float p0 = v0 * W2[c0 * 2 + 0] + v1 * W2[c1 * 2 + 0];
    float p1 = v0 * W2[c0 * 2 + 1] + v1 * W2[c1 * 2 + 1];
    #pragma unroll
    for (int o = 16; o > 0; o >>= 1) {
        p0 += __shfl_down_sync(0xffffffffu, p0, o);
        p1 += __shfl_down_sync(0xffffffffu, p1, o);
    }
    if (lane == 0) {
        g_h3[n * 2 + 0] = p0;
        g_h3[n * 2 + 1] = p1;
        g_as2[n] = p0 * as2[0] + p1 * as2[1];
        g_ad2[n] = p0 * ad2[0] + p1 * ad2[1];
    }
}

// ---------------- layer-2 aggregation (atomic-free) + output ------------------
__global__ __launch_bounds__(256) void k_agg2(
    float* __restrict__ out, const float* __restrict__ b2) {

    int lane = threadIdx.x & 31;
    int n = blockIdx.x * 8 + (threadIdx.x >> 5);
    if (n >= NN) return;

    float ad = g_ad2[n];
    int start = g_offs[n];
    int end = start + g_deg[n];

    float a0 = 0.f, a1 = 0.f, wsum = 0.f;
    for (int i = start + lane; i < end; i += 32) {
        int s = __ldg(g_csr_src + i);
        float w = __expf(lrelu(__ldg(g_as2 + s) + ad));
        float2 hv = *(const float2*)(g_h3 + s * 2);
        a0 += w * hv.x;
        a1 += w * hv.y;
        wsum += w;
    }
    #pragma unroll
    for (int o = 16; o > 0; o >>= 1) {
        a0   += __shfl_down_sync(0xffffffffu, a0, o);
        a1   += __shfl_down_sync(0xffffffffu, a1, o);
        wsum += __shfl_down_sync(0xffffffffu, wsum, o);
    }
    if (lane == 0) {
        float inv = 1.0f / (wsum + 1e-16f);
        out[n * 2 + 0] = a0 * inv + b2[0];
        out[n * 2 + 1] = a1 * inv + b2[1];
    }
}

// ---------------- launch ------------------------------------------------------
extern "C" void kernel_launch(void* const* d_in, const int* in_sizes, int n_in,
                              void* d_out, int out_size) {
    const float* x    = (const float*)d_in[0];
    const int*   ei   = (const int*)  d_in[1];
    const float* W1   = (const float*)d_in[2];
    const float* as1  = (const float*)d_in[3];
    const float* ad1  = (const float*)d_in[4];
    const float* b1   = (const float*)d_in[5];
    const float* W2   = (const float*)d_in[6];
    const float* as2  = (const float*)d_in[7];
    const float* ad2  = (const float*)d_in[8];
    const float* b2   = (const float*)d_in[9];
    float* out = (float*)d_out;

    // One-time host-side resources (host objects only; no device allocation).
    static cudaStream_t s2 = nullptr;
    static cudaEvent_t evFork = nullptr, evJoin = nullptr;
    if (!s2) {
        cudaStreamCreateWithFlags(&s2, cudaStreamNonBlocking);
        cudaEventCreateWithFlags(&evFork, cudaEventDisableTiming);
        cudaEventCreateWithFlags(&evJoin, cudaEventDisableTiming);
        cudaFuncSetAttribute(k_gemm1,
            cudaFuncAttributeMaxDynamicSharedMemorySize, GEMM_SMEM);
    }

    const int T = 256;

    // Fork: CSR build chain (depends only on ei) on s2, concurrent with GEMM.
    cudaEventRecord(evFork, 0);
    cudaStreamWaitEvent(s2, evFork, 0);

    k_gemm1<<<(NN + GNODES - 1) / GNODES, T, GEMM_SMEM>>>(x, W1, as1, ad1);

    k_init<<<(NN + T - 1) / T, T, 0, s2>>>();
    k_count<<<(ETOT / 4 + T - 1) / T, T, 0, s2>>>(ei);
    k_scan1<<<NBLK, SCAN_BLK, 0, s2>>>();
    k_scan2<<<1, 256, 0, s2>>>();
    k_scan3<<<(NN + T - 1) / T, T, 0, s2>>>();
    k_scatter<<<(ETOT / 4 + T - 1) / T, T, 0, s2>>>(ei);

    // Join
    cudaEventRecord(evJoin, s2);
    cudaStreamWaitEvent(0, evJoin, 0);

    k_agg1<<<(NN + 7) / 8, T>>>(b1, W2, as2, ad2);
    k_agg2<<<(NN + 7) / 8, T>>>(out, b2);
}

// round 8
// speedup vs baseline: 2.1676x; 1.1167x over previous
#include <cuda_runtime.h>
#include <cuda_fp16.h>
#include <math.h>

#define NN 100000
#define EE 1600000
#define ETOT (EE + NN)
#define DIM 128
#define HID 16
#define HEADS 4
#define F1 (HEADS * HID)   // 64
#define NEG 0.2f

#define SCAN_BLK 512
#define NBLK ((NN + SCAN_BLK - 1) / SCAN_BLK)   // 196

// gemm tiling: 128 nodes/block, 128 threads, 8 nodes x 8 channels per thread
#define GN 128
#define XPITCH 129
#define GEMM_SMEM ((GN * XPITCH + DIM * F1) * 4)   // 98816 bytes

// ---------------- scratch (static device globals; no allocation) -------------
__device__ __align__(16) __half g_h1h[NN * F1];   // layer-1 features (fp16)
__device__ __align__(16) float g_as1[NN * HEADS];
__device__ __align__(16) float g_ad1[NN * HEADS];
__device__ __align__(16) float g_h3[NN * 2];      // layer-2 transformed features
__device__ float g_as2[NN];
__device__ float g_ad2[NN];

__device__ int g_deg[NN];
__device__ int g_offs[NN + 1];
__device__ int g_cur[NN];
__device__ int g_bsum[256];
__device__ int g_bpre[256];
__device__ int g_csr_src[ETOT];

// ---------------- helpers ----------------------------------------------------
__device__ __forceinline__ float lrelu(float v) {
    return v > 0.0f ? v : NEG * v;
}

__device__ __forceinline__ unsigned long long packf2(float lo, float hi) {
    unsigned long long r;
    asm("mov.b64 %0, {%1, %2};" : "=l"(r) : "f"(lo), "f"(hi));
    return r;
}
__device__ __forceinline__ void unpackf2(unsigned long long v, float& lo, float& hi) {
    asm("mov.b64 {%0, %1}, %2;" : "=f"(lo), "=f"(hi) : "l"(v));
}
__device__ __forceinline__ void fmaf2(unsigned long long& d, unsigned long long a,
                                      unsigned long long b) {
    asm("fma.rn.f32x2 %0, %1, %2, %0;" : "+l"(d) : "l"(a), "l"(b));
}

// ---------------- kernels ----------------------------------------------------

// h1 = x @ W1 (register-tiled 8 nodes x 8 ch per thread, packed f32x2 FMA).
// fp32 math, fp16 store; alpha_s1/alpha_d1 per (node, head).
__global__ __launch_bounds__(128, 2) void k_gemm1(
    const float* __restrict__ x, const float* __restrict__ W1,
    const float* __restrict__ asrc, const float* __restrict__ adst) {

    extern __shared__ float sm[];
    float* xs = sm;                    // [GN][XPITCH]
    float* Ws = sm + GN * XPITCH;      // [DIM][F1] row-major

    int tid = threadIdx.x;
    int n0 = blockIdx.x * GN;

    // load W (contiguous float4 copy)
    #pragma unroll
    for (int i = tid; i < DIM * F1 / 4; i += 128)
        ((float4*)Ws)[i] = ((const float4*)W1)[i];

    // load x tile: 128 rows x 32 float4, coalesced; pitch-129 scalar stores
    for (int i = tid; i < GN * 32; i += 128) {
        int r = i >> 5, c4 = i & 31;
        float4 v = (n0 + r < NN)
                 ? ((const float4*)(x + (size_t)(n0 + r) * DIM))[c4]
                 : make_float4(0.f, 0.f, 0.f, 0.f);
        float* dp = xs + r * XPITCH + c4 * 4;
        dp[0] = v.x; dp[1] = v.y; dp[2] = v.z; dp[3] = v.w;
    }
    __syncthreads();

    int ct = tid & 7;     // channel group: channels [ct*8, ct*8+8)
    int nt = tid >> 3;    // node group: nodes nt*8 .. nt*8+7 (local)

    unsigned long long acc[8][4];
    #pragma unroll
    for (int j = 0; j < 8; j++)
        #pragma unroll
        for (int p = 0; p < 4; p++) acc[j][p] = 0ULL;

    const float* xb = xs + nt * 8 * XPITCH;

    #pragma unroll 2
    for (int k = 0; k < DIM; k++) {
        float4 w0 = *(const float4*)(Ws + k * F1 + ct * 8);
        float4 w1 = *(const float4*)(Ws + k * F1 + ct * 8 + 4);
        unsigned long long wp[4];
        wp[0] = packf2(w0.x, w0.y);
        wp[1] = packf2(w0.z, w0.w);
        wp[2] = packf2(w1.x, w1.y);
        wp[3] = packf2(w1.z, w1.w);
        #pragma unroll
        for (int j = 0; j < 8; j++) {
            float xv = xb[j * XPITCH + k];
            unsigned long long xx = packf2(xv, xv);
            fmaf2(acc[j][0], xx, wp[0]);
            fmaf2(acc[j][1], xx, wp[1]);
            fmaf2(acc[j][2], xx, wp[2]);
            fmaf2(acc[j][3], xx, wp[3]);
        }
    }

    // attention vectors for this thread's 8 channels
    float ar[8], dr[8];
    #pragma unroll
    for (int i = 0; i < 8; i++) {
        ar[i] = __ldg(asrc + ct * 8 + i);
        dr[i] = __ldg(adst + ct * 8 + i);
    }

    // epilogue: fp16 store + per-head logits (heads span 16 ch = 2 ct groups)
    #pragma unroll
    for (int j = 0; j < 8; j++) {
        int n = n0 + nt * 8 + j;
        float a[8];
        unpackf2(acc[j][0], a[0], a[1]);
        unpackf2(acc[j][1], a[2], a[3]);
        unpackf2(acc[j][2], a[4], a[5]);
        unpackf2(acc[j][3], a[6], a[7]);

        float ps = 0.f, pd = 0.f;
        #pragma unroll
        for (int i = 0; i < 8; i++) {
            ps += a[i] * ar[i];
            pd += a[i] * dr[i];
        }
        // combine the two ct-groups of each head (lane xor 1 flips ct bit0)
        ps += __shfl_xor_sync(0xffffffffu, ps, 1);
        pd += __shfl_xor_sync(0xffffffffu, pd, 1);

        if (n < NN) {
            union { __half2 h2[4]; uint4 u; } pk;
            pk.h2[0] = __floats2half2_rn(a[0], a[1]);
            pk.h2[1] = __floats2half2_rn(a[2], a[3]);
            pk.h2[2] = __floats2half2_rn(a[4], a[5]);
            pk.h2[3] = __floats2half2_rn(a[6], a[7]);
            *(uint4*)(g_h1h + (size_t)n * F1 + ct * 8) = pk.u;
            if ((ct & 1) == 0) {
                int h = ct >> 1;
                g_as1[n * HEADS + h] = ps;
                g_ad1[n * HEADS + h] = pd;
            }
        }
    }
}

// ---------------- CSR build ---------------------------------------------------
__global__ void k_count(const int* __restrict__ ei) {
    int t = blockIdx.x * blockDim.x + threadIdx.x;
    if (t >= ETOT / 4) return;
    int e = t * 4;
    if (e < EE) {
        int4 d4 = *(const int4*)(ei + EE + e);
        atomicAdd(&g_deg[d4.x], 1);
        atomicAdd(&g_deg[d4.y], 1);
        atomicAdd(&g_deg[d4.z], 1);
        atomicAdd(&g_deg[d4.w], 1);
    } else {
        int n = e - EE;
        atomicAdd(&g_deg[n + 0], 1);
        atomicAdd(&g_deg[n + 1], 1);
        atomicAdd(&g_deg[n + 2], 1);
        atomicAdd(&g_deg[n + 3], 1);
    }
}

// scan1 also zeroes g_deg (leaves it ready for the next replay; static init
// covers the very first call)
__global__ __launch_bounds__(SCAN_BLK) void k_scan1() {
    __shared__ int sh[SCAN_BLK];
    int t = threadIdx.x;
    int i = blockIdx.x * SCAN_BLK + t;
    int v = 0;
    if (i < NN) { v = g_deg[i]; g_deg[i] = 0; }
    sh[t] = v;
    __syncthreads();
    #pragma unroll
    for (int off = 1; off < SCAN_BLK; off <<= 1) {
        int add = (t >= off) ? sh[t - off] : 0;
        __syncthreads();
        sh[t] += add;
        __syncthreads();
    }
    if (i < NN) g_offs[i] = sh[t] - v;   // exclusive
    if (t == SCAN_BLK - 1) g_bsum[blockIdx.x] = sh[t];
}

__global__ __launch_bounds__(256) void k_scan2() {
    __shared__ int sh[256];
    int t = threadIdx.x;
    int v = (t < NBLK) ? g_bsum[t] : 0;
    sh[t] = v;
    __syncthreads();
    #pragma unroll
    for (int off = 1; off < 256; off <<= 1) {
        int add = (t >= off) ? sh[t - off] : 0;
        __syncthreads();
        sh[t] += add;
        __syncthreads();
    }
    if (t < NBLK) g_bpre[t] = sh[t] - v;  // exclusive
}

__global__ void k_scan3() {
    int i = blockIdx.x * blockDim.x + threadIdx.x;
    if (i >= NN) return;
    int o = g_offs[i] + g_bpre[i / SCAN_BLK];
    g_offs[i] = o;
    g_cur[i] = o;
    if (i == 0) g_offs[NN] = ETOT;   // sentinel
}

__global__ void k_scatter(const int* __restrict__ ei) {
    int t = blockIdx.x * blockDim.x + threadIdx.x;
    if (t >= ETOT / 4) return;
    int e = t * 4;
    int s[4], d[4];
    if (e < EE) {
        int4 s4 = *(const int4*)(ei + e);
        int4 d4 = *(const int4*)(ei + EE + e);
        s[0] = s4.x; s[1] = s4.y; s[2] = s4.z; s[3] = s4.w;
        d[0] = d4.x; d[1] = d4.y; d[2] = d4.z; d[3] = d4.w;
    } else {
        int n = e - EE;
        #pragma unroll
        for (int j = 0; j < 4; j++) { s[j] = n + j; d[j] = n + j; }
    }
    #pragma unroll
    for (int j = 0; j < 4; j++) {
        int pos = atomicAdd(&g_cur[d[j]], 1);
        g_csr_src[pos] = s[j];
    }
}

// ---------------- layer-1 aggregation (atomic-free) + fused l2prep ------------
// One warp per dst node. Lane owns channels (2*lane, 2*lane+1); head = lane>>3.
__global__ __launch_bounds__(256) void k_agg1(
    const float* __restrict__ b1, const float* __restrict__ W2,
    const float* __restrict__ as2, const float* __restrict__ ad2) {

    int lane = threadIdx.x & 31;
    int n = blockIdx.x * 8 + (threadIdx.x >> 5);
    if (n >= NN) return;

    int h = lane >> 3;
    float adh = g_ad1[n * 4 + h];
    int start = __ldg(g_offs + n);
    int end = __ldg(g_offs + n + 1);
    int c = 2 * lane;

    float acc0 = 0.f, acc1 = 0.f, wsum = 0.f;
    int i = start;
    for (; i + 4 <= end; i += 4) {
        int s0 = __ldg(g_csr_src + i + 0);
        int s1 = __ldg(g_csr_src + i + 1);
        int s2 = __ldg(g_csr_src + i + 2);
        int s3 = __ldg(g_csr_src + i + 3);
        float e0 = __ldg(g_as1 + s0 * 4 + h);
        float e1 = __ldg(g_as1 + s1 * 4 + h);
        float e2 = __ldg(g_as1 + s2 * 4 + h);
        float e3 = __ldg(g_as1 + s3 * 4 + h);
        float2 q0 = __half22float2(*(const __half2*)(g_h1h + (size_t)s0 * F1 + c));
        float2 q1 = __half22float2(*(const __half2*)(g_h1h + (size_t)s1 * F1 + c));
        float2 q2 = __half22float2(*(const __half2*)(g_h1h + (size_t)s2 * F1 + c));
        float2 q3 = __half22float2(*(const __half2*)(g_h1h + (size_t)s3 * F1 + c));
        float w0 = __expf(lrelu(e0 + adh));
        float w1 = __expf(lrelu(e1 + adh));
        float w2 = __expf(lrelu(e2 + adh));
        float w3 = __expf(lrelu(e3 + adh));
        acc0 += w0 * q0.x + w1 * q1.x;
        acc1 += w0 * q0.y + w1 * q1.y;
        acc0 += w2 * q2.x + w3 * q3.x;
        acc1 += w2 * q2.y + w3 * q3.y;
        wsum += (w0 + w1) + (w2 + w3);
    }
    for (; i < end; i++) {
        int s = __ldg(g_csr_src + i);
        float as = __ldg(g_as1 + s * 4 + h);
        float w = __expf(lrelu(as + adh));
        float2 hv = __half22float2(*(const __half2*)(g_h1h + (size_t)s * F1 + c));
        acc0 += w * hv.x;
        acc1 += w * hv.y;
        wsum += w;
    }

    float inv = 1.0f / (wsum + 1e-16f);
    int c0 = c, c1 = c + 1;
    float v0 = acc0 * inv + b1[c0];
    float v1 = acc1 * inv + b1[c1];
    v0 = v0 > 0.f ? v0 : expm1f(v0);          // ELU
    v1 = v1 > 0.f ? v1 : expm1f(v1);

    float p0 = v0 * W2[c0 * 2 + 0] + v1 * W2[c1 * 2 + 0];
    float p1 = v0 * W2[c0 * 2 + 1] + v1 * W2[c1 * 2 + 1];
    #pragma unroll
    for (int o = 16; o > 0; o >>= 1) {
        p0 += __shfl_down_sync(0xffffffffu, p0, o);
        p1 += __shfl_down_sync(0xffffffffu, p1, o);
    }
    if (lane == 0) {
        g_h3[n * 2 + 0] = p0;
        g_h3[n * 2 + 1] = p1;
        g_as2[n] = p0 * as2[0] + p1 * as2[1];
        g_ad2[n] = p0 * ad2[0] + p1 * ad2[1];
    }
}

// ---------------- layer-2 aggregation (atomic-free) + output ------------------
__global__ __launch_bounds__(256) void k_agg2(
    float* __restrict__ out, const float* __restrict__ b2) {

    int lane = threadIdx.x & 31;
    int n = blockIdx.x * 8 + (threadIdx.x >> 5);
    if (n >= NN) return;

    float ad = g_ad2[n];
    int start = __ldg(g_offs + n);
    int end = __ldg(g_offs + n + 1);

    float a0 = 0.f, a1 = 0.f, wsum = 0.f;
    for (int i = start + lane; i < end; i += 32) {
        int s = __ldg(g_csr_src + i);
        float w = __expf(lrelu(__ldg(g_as2 + s) + ad));
        float2 hv = *(const float2*)(g_h3 + s * 2);
        a0 += w * hv.x;
        a1 += w * hv.y;
        wsum += w;
    }
    #pragma unroll
    for (int o = 16; o > 0; o >>= 1) {
        a0   += __shfl_down_sync(0xffffffffu, a0, o);
        a1   += __shfl_down_sync(0xffffffffu, a1, o);
        wsum += __shfl_down_sync(0xffffffffu, wsum, o);
    }
    if (lane == 0) {
        float inv = 1.0f / (wsum + 1e-16f);
        out[n * 2 + 0] = a0 * inv + b2[0];
        out[n * 2 + 1] = a1 * inv + b2[1];
    }
}

// ---------------- launch ------------------------------------------------------
extern "C" void kernel_launch(void* const* d_in, const int* in_sizes, int n_in,
                              void* d_out, int out_size) {
    const float* x    = (const float*)d_in[0];
    const int*   ei   = (const int*)  d_in[1];
    const float* W1   = (const float*)d_in[2];
    const float* as1  = (const float*)d_in[3];
    const float* ad1  = (const float*)d_in[4];
    const float* b1   = (const float*)d_in[5];
    const float* W2   = (const float*)d_in[6];
    const float* as2  = (const float*)d_in[7];
    const float* ad2  = (const float*)d_in[8];
    const float* b2   = (const float*)d_in[9];
    float* out = (float*)d_out;

    // One-time host-side resources (host objects only; no device allocation).
    static cudaStream_t s2 = nullptr;
    static cudaEvent_t evFork = nullptr, evJoin = nullptr;
    if (!s2) {
        cudaStreamCreateWithFlags(&s2, cudaStreamNonBlocking);
        cudaEventCreateWithFlags(&evFork, cudaEventDisableTiming);
        cudaEventCreateWithFlags(&evJoin, cudaEventDisableTiming);
        cudaFuncSetAttribute(k_gemm1,
            cudaFuncAttributeMaxDynamicSharedMemorySize, GEMM_SMEM);
    }

    const int T = 256;

    // Fork: CSR build chain (depends only on ei) on s2, concurrent with GEMM.
    cudaEventRecord(evFork, 0);
    cudaStreamWaitEvent(s2, evFork, 0);

    k_gemm1<<<(NN + GN - 1) / GN, 128, GEMM_SMEM>>>(x, W1, as1, ad1);

    k_count<<<(ETOT / 4 + T - 1) / T, T, 0, s2>>>(ei);
    k_scan1<<<NBLK, SCAN_BLK, 0, s2>>>();
    k_scan2<<<1, 256, 0, s2>>>();
    k_scan3<<<(NN + T - 1) / T, T, 0, s2>>>();
    k_scatter<<<(ETOT / 4 + T - 1) / T, T, 0, s2>>>(ei);

    // Join
    cudaEventRecord(evJoin, s2);
    cudaStreamWaitEvent(0, evJoin, 0);

    k_agg1<<<(NN + 7) / 8, T>>>(b1, W2, as2, ad2);
    k_agg2<<<(NN + 7) / 8, T>>>(out, b2);
}

// round 9
// speedup vs baseline: 2.2267x; 1.0272x over previous
#include <cuda_runtime.h>
#include <cuda_fp16.h>
#include <math.h>

#define NN 100000
#define EE 1600000
#define ETOT (EE + NN)
#define DIM 128
#define HID 16
#define HEADS 4
#define F1 (HEADS * HID)   // 64
#define NEG 0.2f

#define SCAN_BLK 512
#define NBLK ((NN + SCAN_BLK - 1) / SCAN_BLK)   // 196

// gemm tiling: 128 nodes/block, 128 threads, 8 nodes x 8 channels per thread
#define GN 128
#define XPITCH 129
#define GEMM_SMEM ((GN * XPITCH + DIM * F1) * 4)   // 98816 bytes

// ---------------- scratch (static device globals; no allocation) -------------
__device__ __align__(16) __half g_h1h[NN * F1];   // layer-1 features (fp16)
__device__ __align__(16) float g_as1[NN * HEADS];
__device__ __align__(16) float g_ad1[NN * HEADS];
__device__ __align__(16) float g_h3[NN * 2];      // layer-2 transformed features
__device__ float g_as2[NN];
__device__ float g_ad2[NN];

__device__ int g_deg[NN];
__device__ int g_offs[NN + 1];
__device__ int g_cur[NN];
__device__ int g_bsum[256];
__device__ unsigned long long g_ctr = 0ULL;   // epoch ticket counter (never reset)
__device__ int g_csr_src[ETOT];

// ---------------- helpers ----------------------------------------------------
__device__ __forceinline__ float lrelu(float v) {
    return v > 0.0f ? v : NEG * v;
}

__device__ __forceinline__ unsigned long long packf2(float lo, float hi) {
    unsigned long long r;
    asm("mov.b64 %0, {%1, %2};" : "=l"(r) : "f"(lo), "f"(hi));
    return r;
}
__device__ __forceinline__ void unpackf2(unsigned long long v, float& lo, float& hi) {
    asm("mov.b64 {%0, %1}, %2;" : "=f"(lo), "=f"(hi) : "l"(v));
}
__device__ __forceinline__ void fmaf2(unsigned long long& d, unsigned long long a,
                                      unsigned long long b) {
    asm("fma.rn.f32x2 %0, %1, %2, %0;" : "+l"(d) : "l"(a), "l"(b));
}

// ---------------- kernels ----------------------------------------------------

// h1 = x @ W1 (register-tiled 8 nodes x 8 ch per thread, packed f32x2 FMA).
__global__ __launch_bounds__(128, 2) void k_gemm1(
    const float* __restrict__ x, const float* __restrict__ W1,
    const float* __restrict__ asrc, const float* __restrict__ adst) {

    extern __shared__ float sm[];
    float* xs = sm;                    // [GN][XPITCH]
    float* Ws = sm + GN * XPITCH;      // [DIM][F1] row-major

    int tid = threadIdx.x;
    int n0 = blockIdx.x * GN;

    #pragma unroll
    for (int i = tid; i < DIM * F1 / 4; i += 128)
        ((float4*)Ws)[i] = ((const float4*)W1)[i];

    for (int i = tid; i < GN * 32; i += 128) {
        int r = i >> 5, c4 = i & 31;
        float4 v = (n0 + r < NN)
                 ? ((const float4*)(x + (size_t)(n0 + r) * DIM))[c4]
                 : make_float4(0.f, 0.f, 0.f, 0.f);
        float* dp = xs + r * XPITCH + c4 * 4;
        dp[0] = v.x; dp[1] = v.y; dp[2] = v.z; dp[3] = v.w;
    }
    __syncthreads();

    int ct = tid & 7;
    int nt = tid >> 3;

    unsigned long long acc[8][4];
    #pragma unroll
    for (int j = 0; j < 8; j++)
        #pragma unroll
        for (int p = 0; p < 4; p++) acc[j][p] = 0ULL;

    const float* xb = xs + nt * 8 * XPITCH;

    #pragma unroll 2
    for (int k = 0; k < DIM; k++) {
        float4 w0 = *(const float4*)(Ws + k * F1 + ct * 8);
        float4 w1 = *(const float4*)(Ws + k * F1 + ct * 8 + 4);
        unsigned long long wp[4];
        wp[0] = packf2(w0.x, w0.y);
        wp[1] = packf2(w0.z, w0.w);
        wp[2] = packf2(w1.x, w1.y);
        wp[3] = packf2(w1.z, w1.w);
        #pragma unroll
        for (int j = 0; j < 8; j++) {
            float xv = xb[j * XPITCH + k];
            unsigned long long xx = packf2(xv, xv);
            fmaf2(acc[j][0], xx, wp[0]);
            fmaf2(acc[j][1], xx, wp[1]);
            fmaf2(acc[j][2], xx, wp[2]);
            fmaf2(acc[j][3], xx, wp[3]);
        }
    }

    float ar[8], dr[8];
    #pragma unroll
    for (int i = 0; i < 8; i++) {
        ar[i] = __ldg(asrc + ct * 8 + i);
        dr[i] = __ldg(adst + ct * 8 + i);
    }

    #pragma unroll
    for (int j = 0; j < 8; j++) {
        int n = n0 + nt * 8 + j;
        float a[8];
        unpackf2(acc[j][0], a[0], a[1]);
        unpackf2(acc[j][1], a[2], a[3]);
        unpackf2(acc[j][2], a[4], a[5]);
        unpackf2(acc[j][3], a[6], a[7]);

        float ps = 0.f, pd = 0.f;
        #pragma unroll
        for (int i = 0; i < 8; i++) {
            ps += a[i] * ar[i];
            pd += a[i] * dr[i];
        }
        ps += __shfl_xor_sync(0xffffffffu, ps, 1);
        pd += __shfl_xor_sync(0xffffffffu, pd, 1);

        if (n < NN) {
            union { __half2 h2[4]; uint4 u; } pk;
            pk.h2[0] = __floats2half2_rn(a[0], a[1]);
            pk.h2[1] = __floats2half2_rn(a[2], a[3]);
            pk.h2[2] = __floats2half2_rn(a[4], a[5]);
            pk.h2[3] = __floats2half2_rn(a[6], a[7]);
            *(uint4*)(g_h1h + (size_t)n * F1 + ct * 8) = pk.u;
            if ((ct & 1) == 0) {
                int h = ct >> 1;
                g_as1[n * HEADS + h] = ps;
                g_ad1[n * HEADS + h] = pd;
            }
        }
    }
}

// ---------------- CSR build ---------------------------------------------------
__global__ void k_count(const int* __restrict__ ei) {
    int t = blockIdx.x * blockDim.x + threadIdx.x;
    if (t >= ETOT / 4) return;
    int e = t * 4;
    if (e < EE) {
        int4 d4 = *(const int4*)(ei + EE + e);
        atomicAdd(&g_deg[d4.x], 1);
        atomicAdd(&g_deg[d4.y], 1);
        atomicAdd(&g_deg[d4.z], 1);
        atomicAdd(&g_deg[d4.w], 1);
    } else {
        int n = e - EE;
        atomicAdd(&g_deg[n + 0], 1);
        atomicAdd(&g_deg[n + 1], 1);
        atomicAdd(&g_deg[n + 2], 1);
        atomicAdd(&g_deg[n + 3], 1);
    }
}

// Fused single-pass scan (replaces scan1+scan2+scan3). All NBLK=196 blocks are
// resident simultaneously (even co-running with gemm1), so a grid-wide
// epoch-ticket spin is deadlock-free. Counter is monotonic (replay-safe).
// Also zeroes g_deg for the next replay (static init covers the first call).
__global__ __launch_bounds__(SCAN_BLK) void k_scanF() {
    __shared__ int sh[SCAN_BLK];
    __shared__ int s_prefix;
    int t = threadIdx.x;
    int b = blockIdx.x;
    int i = b * SCAN_BLK + t;
    int v = 0;
    if (i < NN) { v = g_deg[i]; g_deg[i] = 0; }
    sh[t] = v;
    __syncthreads();
    #pragma unroll
    for (int off = 1; off < SCAN_BLK; off <<= 1) {
        int add = (t >= off) ? sh[t - off] : 0;
        __syncthreads();
        sh[t] += add;
        __syncthreads();
    }
    int incl = sh[t];

    if (t == SCAN_BLK - 1) {
        g_bsum[b] = incl;                    // block total
        __threadfence();
        unsigned long long old = atomicAdd(&g_ctr, 1ULL);
        unsigned long long target = (old / NBLK + 1ULL) * NBLK;
        while (atomicAdd(&g_ctr, 0ULL) < target) { }
    }
    __syncthreads();

    // prefix of preceding blocks (volatile: bypass L1, see peers' writes)
    if (t < 32) {
        volatile int* vb = g_bsum;
        int p = 0;
        for (int j = t; j < b; j += 32) p += vb[j];
        #pragma unroll
        for (int o = 16; o > 0; o >>= 1)
            p += __shfl_down_sync(0xffffffffu, p, o);
        if (t == 0) s_prefix = p;
    }
    __syncthreads();

    if (i < NN) {
        int o = s_prefix + incl - v;   // exclusive scan
        g_offs[i] = o;
        g_cur[i] = o;
    }
    if (i == NN - 1) g_offs[NN] = ETOT;   // sentinel
}

__global__ void k_scatter(const int* __restrict__ ei) {
    int t = blockIdx.x * blockDim.x + threadIdx.x;
    if (t >= ETOT / 4) return;
    int e = t * 4;
    int s[4], d[4];
    if (e < EE) {
        int4 s4 = *(const int4*)(ei + e);
        int4 d4 = *(const int4*)(ei + EE + e);
        s[0] = s4.x; s[1] = s4.y; s[2] = s4.z; s[3] = s4.w;
        d[0] = d4.x; d[1] = d4.y; d[2] = d4.z; d[3] = d4.w;
    } else {
        int n = e - EE;
        #pragma unroll
        for (int j = 0; j < 4; j++) { s[j] = n + j; d[j] = n + j; }
    }
    #pragma unroll
    for (int j = 0; j < 4; j++) {
        int pos = atomicAdd(&g_cur[d[j]], 1);
        g_csr_src[pos] = s[j];
    }
}

// ---------------- layer-1 aggregation (atomic-free) + fused l2prep ------------
// One warp per dst node. Lane owns channels (2*lane, 2*lane+1); head = lane>>3.
__global__ __launch_bounds__(256) void k_agg1(
    const float* __restrict__ b1, const float* __restrict__ W2,
    const float* __restrict__ as2, const float* __restrict__ ad2) {

    int lane = threadIdx.x & 31;
    int n = blockIdx.x * 8 + (threadIdx.x >> 5);
    if (n >= NN) return;

    int h = lane >> 3;
    float adh = g_ad1[n * 4 + h];
    int start = __ldg(g_offs + n);
    int end = __ldg(g_offs + n + 1);
    int c = 2 * lane;

    float acc0 = 0.f, acc1 = 0.f, wsum = 0.f;
    int i = start;
    for (; i + 4 <= end; i += 4) {
        int s0 = __ldg(g_csr_src + i + 0);
        int s1 = __ldg(g_csr_src + i + 1);
        int s2 = __ldg(g_csr_src + i + 2);
        int s3 = __ldg(g_csr_src + i + 3);
        float e0 = __ldg(g_as1 + s0 * 4 + h);
        float e1 = __ldg(g_as1 + s1 * 4 + h);
        float e2 = __ldg(g_as1 + s2 * 4 + h);
        float e3 = __ldg(g_as1 + s3 * 4 + h);
        float2 q0 = __half22float2(*(const __half2*)(g_h1h + (size_t)s0 * F1 + c));
        float2 q1 = __half22float2(*(const __half2*)(g_h1h + (size_t)s1 * F1 + c));
        float2 q2 = __half22float2(*(const __half2*)(g_h1h + (size_t)s2 * F1 + c));
        float2 q3 = __half22float2(*(const __half2*)(g_h1h + (size_t)s3 * F1 + c));
        float w0 = __expf(lrelu(e0 + adh));
        float w1 = __expf(lrelu(e1 + adh));
        float w2 = __expf(lrelu(e2 + adh));
        float w3 = __expf(lrelu(e3 + adh));
        acc0 += w0 * q0.x + w1 * q1.x;
        acc1 += w0 * q0.y + w1 * q1.y;
        acc0 += w2 * q2.x + w3 * q3.x;
        acc1 += w2 * q2.y + w3 * q3.y;
        wsum += (w0 + w1) + (w2 + w3);
    }
    for (; i < end; i++) {
        int s = __ldg(g_csr_src + i);
        float as = __ldg(g_as1 + s * 4 + h);
        float w = __expf(lrelu(as + adh));
        float2 hv = __half22float2(*(const __half2*)(g_h1h + (size_t)s * F1 + c));
        acc0 += w * hv.x;
        acc1 += w * hv.y;
        wsum += w;
    }

    float inv = 1.0f / (wsum + 1e-16f);
    int c0 = c, c1 = c + 1;
    float v0 = acc0 * inv + b1[c0];
    float v1 = acc1 * inv + b1[c1];
    v0 = v0 > 0.f ? v0 : expm1f(v0);          // ELU
    v1 = v1 > 0.f ? v1 : expm1f(v1);

    float p0 = v0 * W2[c0 * 2 + 0] + v1 * W2[c1 * 2 + 0];
    float p1 = v0 * W2[c0 * 2 + 1] + v1 * W2[c1 * 2 + 1];
    #pragma unroll
    for (int o = 16; o > 0; o >>= 1) {
        p0 += __shfl_down_sync(0xffffffffu, p0, o);
        p1 += __shfl_down_sync(0xffffffffu, p1, o);
    }
    if (lane == 0) {
        g_h3[n * 2 + 0] = p0;
        g_h3[n * 2 + 1] = p1;
        g_as2[n] = p0 * as2[0] + p1 * as2[1];
        g_ad2[n] = p0 * ad2[0] + p1 * ad2[1];
    }
}

// ---------------- layer-2 aggregation + output: half-warp per node ------------
__global__ __launch_bounds__(256) void k_agg2(
    float* __restrict__ out, const float* __restrict__ b2) {

    int sub = threadIdx.x & 15;
    int n = blockIdx.x * 16 + (threadIdx.x >> 4);
    if (n >= NN) return;

    float ad = g_ad2[n];
    int start = __ldg(g_offs + n);
    int end = __ldg(g_offs + n + 1);

    float a0 = 0.f, a1 = 0.f, wsum = 0.f;
    for (int i = start + sub; i < end; i += 16) {
        int s = __ldg(g_csr_src + i);
        float w = __expf(lrelu(__ldg(g_as2 + s) + ad));
        float2 hv = *(const float2*)(g_h3 + s * 2);
        a0 += w * hv.x;
        a1 += w * hv.y;
        wsum += w;
    }
    #pragma unroll
    for (int o = 8; o > 0; o >>= 1) {
        a0   += __shfl_down_sync(0xffffffffu, a0, o, 16);
        a1   += __shfl_down_sync(0xffffffffu, a1, o, 16);
        wsum += __shfl_down_sync(0xffffffffu, wsum, o, 16);
    }
    if (sub == 0) {
        float inv = 1.0f / (wsum + 1e-16f);
        out[n * 2 + 0] = a0 * inv + b2[0];
        out[n * 2 + 1] = a1 * inv + b2[1];
    }
}

// ---------------- launch ------------------------------------------------------
extern "C" void kernel_launch(void* const* d_in, const int* in_sizes, int n_in,
                              void* d_out, int out_size) {
    const float* x    = (const float*)d_in[0];
    const int*   ei   = (const int*)  d_in[1];
    const float* W1   = (const float*)d_in[2];
    const float* as1  = (const float*)d_in[3];
    const float* ad1  = (const float*)d_in[4];
    const float* b1   = (const float*)d_in[5];
    const float* W2   = (const float*)d_in[6];
    const float* as2  = (const float*)d_in[7];
    const float* ad2  = (const float*)d_in[8];
    const float* b2   = (const float*)d_in[9];
    float* out = (float*)d_out;

    // One-time host-side resources (host objects only; no device allocation).
    static cudaStream_t s2 = nullptr;
    static cudaEvent_t evFork = nullptr, evJoin = nullptr;
    if (!s2) {
        cudaStreamCreateWithFlags(&s2, cudaStreamNonBlocking);
        cudaEventCreateWithFlags(&evFork, cudaEventDisableTiming);
        cudaEventCreateWithFlags(&evJoin, cudaEventDisableTiming);
        cudaFuncSetAttribute(k_gemm1,
            cudaFuncAttributeMaxDynamicSharedMemorySize, GEMM_SMEM);
    }

    const int T = 256;

    // Fork: CSR build chain (depends only on ei) on s2, concurrent with GEMM.
    cudaEventRecord(evFork, 0);
    cudaStreamWaitEvent(s2, evFork, 0);

    k_gemm1<<<(NN + GN - 1) / GN, 128, GEMM_SMEM>>>(x, W1, as1, ad1);

    k_count<<<(ETOT / 4 + T - 1) / T, T, 0, s2>>>(ei);
    k_scanF<<<NBLK, SCAN_BLK, 0, s2>>>();
    k_scatter<<<(ETOT / 4 + T - 1) / T, T, 0, s2>>>(ei);

    // Join
    cudaEventRecord(evJoin, s2);
    cudaStreamWaitEvent(0, evJoin, 0);

    k_agg1<<<(NN + 7) / 8, T>>>(b1, W2, as2, ad2);
    k_agg2<<<(NN + 15) / 16, T>>>(out, b2);
}

// round 10
// speedup vs baseline: 2.2578x; 1.0140x over previous
#include <cuda_runtime.h>
#include <cuda_fp16.h>
#include <math.h>

#define NN 100000
#define EE 1600000
#define ETOT (EE + NN)
#define DIM 128
#define HID 16
#define HEADS 4
#define F1 (HEADS * HID)   // 64
#define NEG 0.2f

#define SCAN_BLK 512
#define NBLK ((NN + SCAN_BLK - 1) / SCAN_BLK)   // 196

// gemm tiling: 128 nodes/block, 128 threads, 8 nodes x 8 channels per thread
#define GN 128
#define XPITCH 129
#define GEMM_SMEM ((GN * XPITCH + DIM * F1) * 4)   // 98816 bytes

// ---------------- scratch (static device globals; no allocation) -------------
__device__ __align__(16) __half g_h1h[NN * F1];   // layer-1 features (fp16)
__device__ __align__(16) float g_as1[NN * HEADS];
__device__ __align__(16) float g_ad1[NN * HEADS];
__device__ __align__(16) float g_h3[NN * 2];      // layer-2 transformed features
__device__ float g_as2[NN];
__device__ float g_ad2[NN];

__device__ int g_deg[NN];
__device__ int g_offs[NN + 1];
__device__ int g_cur[NN];
__device__ int g_bsum[256];
__device__ unsigned long long g_ctr = 0ULL;   // epoch ticket counter (never reset)
__device__ int g_csr_src[ETOT];

// ---------------- helpers ----------------------------------------------------
__device__ __forceinline__ float lrelu(float v) {
    return v > 0.0f ? v : NEG * v;
}

__device__ __forceinline__ unsigned long long packf2(float lo, float hi) {
    unsigned long long r;
    asm("mov.b64 %0, {%1, %2};" : "=l"(r) : "f"(lo), "f"(hi));
    return r;
}
__device__ __forceinline__ void unpackf2(unsigned long long v, float& lo, float& hi) {
    asm("mov.b64 {%0, %1}, %2;" : "=f"(lo), "=f"(hi) : "l"(v));
}
__device__ __forceinline__ void fmaf2(unsigned long long& d, unsigned long long a,
                                      unsigned long long b) {
    asm("fma.rn.f32x2 %0, %1, %2, %0;" : "+l"(d) : "l"(a), "l"(b));
}

// ---------------- kernels ----------------------------------------------------

// h1 = x @ W1 (register-tiled 8 nodes x 8 ch per thread, packed f32x2 FMA).
__global__ __launch_bounds__(128, 2) void k_gemm1(
    const float* __restrict__ x, const float* __restrict__ W1,
    const float* __restrict__ asrc, const float* __restrict__ adst) {

    extern __shared__ float sm[];
    float* xs = sm;                    // [GN][XPITCH]
    float* Ws = sm + GN * XPITCH;      // [DIM][F1] row-major

    int tid = threadIdx.x;
    int n0 = blockIdx.x * GN;

    #pragma unroll
    for (int i = tid; i < DIM * F1 / 4; i += 128)
        ((float4*)Ws)[i] = ((const float4*)W1)[i];

    for (int i = tid; i < GN * 32; i += 128) {
        int r = i >> 5, c4 = i & 31;
        float4 v = (n0 + r < NN)
                 ? ((const float4*)(x + (size_t)(n0 + r) * DIM))[c4]
                 : make_float4(0.f, 0.f, 0.f, 0.f);
        float* dp = xs + r * XPITCH + c4 * 4;
        dp[0] = v.x; dp[1] = v.y; dp[2] = v.z; dp[3] = v.w;
    }
    __syncthreads();

    int ct = tid & 7;
    int nt = tid >> 3;

    unsigned long long acc[8][4];
    #pragma unroll
    for (int j = 0; j < 8; j++)
        #pragma unroll
        for (int p = 0; p < 4; p++) acc[j][p] = 0ULL;

    const float* xb = xs + nt * 8 * XPITCH;

    #pragma unroll 2
    for (int k = 0; k < DIM; k++) {
        float4 w0 = *(const float4*)(Ws + k * F1 + ct * 8);
        float4 w1 = *(const float4*)(Ws + k * F1 + ct * 8 + 4);
        unsigned long long wp[4];
        wp[0] = packf2(w0.x, w0.y);
        wp[1] = packf2(w0.z, w0.w);
        wp[2] = packf2(w1.x, w1.y);
        wp[3] = packf2(w1.z, w1.w);
        #pragma unroll
        for (int j = 0; j < 8; j++) {
            float xv = xb[j * XPITCH + k];
            unsigned long long xx = packf2(xv, xv);
            fmaf2(acc[j][0], xx, wp[0]);
            fmaf2(acc[j][1], xx, wp[1]);
            fmaf2(acc[j][2], xx, wp[2]);
            fmaf2(acc[j][3], xx, wp[3]);
        }
    }

    float ar[8], dr[8];
    #pragma unroll
    for (int i = 0; i < 8; i++) {
        ar[i] = __ldg(asrc + ct * 8 + i);
        dr[i] = __ldg(adst + ct * 8 + i);
    }

    #pragma unroll
    for (int j = 0; j < 8; j++) {
        int n = n0 + nt * 8 + j;
        float a[8];
        unpackf2(acc[j][0], a[0], a[1]);
        unpackf2(acc[j][1], a[2], a[3]);
        unpackf2(acc[j][2], a[4], a[5]);
        unpackf2(acc[j][3], a[6], a[7]);

        float ps = 0.f, pd = 0.f;
        #pragma unroll
        for (int i = 0; i < 8; i++) {
            ps += a[i] * ar[i];
            pd += a[i] * dr[i];
        }
        ps += __shfl_xor_sync(0xffffffffu, ps, 1);
        pd += __shfl_xor_sync(0xffffffffu, pd, 1);

        if (n < NN) {
            union { __half2 h2[4]; uint4 u; } pk;
            pk.h2[0] = __floats2half2_rn(a[0], a[1]);
            pk.h2[1] = __floats2half2_rn(a[2], a[3]);
            pk.h2[2] = __floats2half2_rn(a[4], a[5]);
            pk.h2[3] = __floats2half2_rn(a[6], a[7]);
            *(uint4*)(g_h1h + (size_t)n * F1 + ct * 8) = pk.u;
            if ((ct & 1) == 0) {
                int h = ct >> 1;
                g_as1[n * HEADS + h] = ps;
                g_ad1[n * HEADS + h] = pd;
            }
        }
    }
}

// ---------------- CSR build ---------------------------------------------------
// 8 edges per thread for MLP (ETOT and EE divisible by 8)
__global__ void k_count(const int* __restrict__ ei) {
    int t = blockIdx.x * blockDim.x + threadIdx.x;
    if (t >= ETOT / 8) return;
    int e = t * 8;
    if (e < EE) {
        int4 a = *(const int4*)(ei + EE + e);
        int4 b = *(const int4*)(ei + EE + e + 4);
        atomicAdd(&g_deg[a.x], 1); atomicAdd(&g_deg[a.y], 1);
        atomicAdd(&g_deg[a.z], 1); atomicAdd(&g_deg[a.w], 1);
        atomicAdd(&g_deg[b.x], 1); atomicAdd(&g_deg[b.y], 1);
        atomicAdd(&g_deg[b.z], 1); atomicAdd(&g_deg[b.w], 1);
    } else {
        int n = e - EE;
        #pragma unroll
        for (int j = 0; j < 8; j++) atomicAdd(&g_deg[n + j], 1);
    }
}

// Fused single-pass scan; all NBLK=196 blocks resident -> grid spin is safe.
// Also zeroes g_deg for the next replay (static init covers the first call).
__global__ __launch_bounds__(SCAN_BLK) void k_scanF() {
    __shared__ int sh[SCAN_BLK];
    __shared__ int s_prefix;
    int t = threadIdx.x;
    int b = blockIdx.x;
    int i = b * SCAN_BLK + t;
    int v = 0;
    if (i < NN) { v = g_deg[i]; g_deg[i] = 0; }
    sh[t] = v;
    __syncthreads();
    #pragma unroll
    for (int off = 1; off < SCAN_BLK; off <<= 1) {
        int add = (t >= off) ? sh[t - off] : 0;
        __syncthreads();
        sh[t] += add;
        __syncthreads();
    }
    int incl = sh[t];

    if (t == SCAN_BLK - 1) {
        g_bsum[b] = incl;
        __threadfence();
        unsigned long long old = atomicAdd(&g_ctr, 1ULL);
        unsigned long long target = (old / NBLK + 1ULL) * NBLK;
        while (atomicAdd(&g_ctr, 0ULL) < target) { }
    }
    __syncthreads();

    if (t < 32) {
        volatile int* vb = g_bsum;
        int p = 0;
        for (int j = t; j < b; j += 32) p += vb[j];
        #pragma unroll
        for (int o = 16; o > 0; o >>= 1)
            p += __shfl_down_sync(0xffffffffu, p, o);
        if (t == 0) s_prefix = p;
    }
    __syncthreads();

    if (i < NN) {
        int o = s_prefix + incl - v;
        g_offs[i] = o;
        g_cur[i] = o;
    }
    if (i == NN - 1) g_offs[NN] = ETOT;
}

// 8 edges per thread for MLP
__global__ void k_scatter(const int* __restrict__ ei) {
    int t = blockIdx.x * blockDim.x + threadIdx.x;
    if (t >= ETOT / 8) return;
    int e = t * 8;
    int s[8], d[8];
    if (e < EE) {
        int4 sa = *(const int4*)(ei + e);
        int4 sb = *(const int4*)(ei + e + 4);
        int4 da = *(const int4*)(ei + EE + e);
        int4 db = *(const int4*)(ei + EE + e + 4);
        s[0]=sa.x; s[1]=sa.y; s[2]=sa.z; s[3]=sa.w;
        s[4]=sb.x; s[5]=sb.y; s[6]=sb.z; s[7]=sb.w;
        d[0]=da.x; d[1]=da.y; d[2]=da.z; d[3]=da.w;
        d[4]=db.x; d[5]=db.y; d[6]=db.z; d[7]=db.w;
    } else {
        int n = e - EE;
        #pragma unroll
        for (int j = 0; j < 8; j++) { s[j] = n + j; d[j] = n + j; }
    }
    int pos[8];
    #pragma unroll
    for (int j = 0; j < 8; j++) pos[j] = atomicAdd(&g_cur[d[j]], 1);
    #pragma unroll
    for (int j = 0; j < 8; j++) g_csr_src[pos[j]] = s[j];
}

// ---------------- layer-1 aggregation + fused l2prep --------------------------
// One warp per dst node; batch-of-8-edge choreography:
//   weight roles:  lane = e*4 + h  (e = lane>>2 in 0..7, h = lane&3)
//   accum roles:   lane owns channels (2*lane, 2*lane+1), head h_acc = lane>>3
__global__ __launch_bounds__(256) void k_agg1(
    const float* __restrict__ b1, const float* __restrict__ W2,
    const float* __restrict__ as2, const float* __restrict__ ad2) {

    const unsigned FULL = 0xffffffffu;
    int lane = threadIdx.x & 31;
    int n = blockIdx.x * 8 + (threadIdx.x >> 5);
    if (n >= NN) return;

    int h_w = lane & 3;        // head for weight role
    int e_w = lane >> 2;       // edge slot for weight role
    int h_acc = lane >> 3;     // head for accumulation role
    int c = 2 * lane;

    float ad_w = __ldg(g_ad1 + n * 4 + h_w);
    int start = __ldg(g_offs + n);
    int end = __ldg(g_offs + n + 1);

    float acc0 = 0.f, acc1 = 0.f, wsum = 0.f;

    for (int base = start; base < end; base += 8) {
        // one LDG: lanes hold csr_src[base + (lane&7)] (clamped in-bounds)
        int li = base + (lane & 7);
        int idx = __ldg(g_csr_src + (li < ETOT ? li : ETOT - 1));

        // one scattered LDG + one expf computes all 8x4 weights
        int s_w = __shfl_sync(FULL, idx, e_w);
        float av = __ldg(g_as1 + s_w * 4 + h_w);
        float w = __expf(lrelu(av + ad_w));
        if (base + e_w >= end) w = 0.f;

        #pragma unroll
        for (int e = 0; e < 8; e++) {
            int s_e = __shfl_sync(FULL, idx, e);
            float w_e = __shfl_sync(FULL, w, e * 4 + h_acc);
            float2 q = __half22float2(
                *(const __half2*)(g_h1h + (size_t)s_e * F1 + c));
            acc0 += w_e * q.x;
            acc1 += w_e * q.y;
            wsum += w_e;
        }
    }

    float inv = 1.0f / (wsum + 1e-16f);
    int c0 = c, c1 = c + 1;
    float v0 = acc0 * inv + b1[c0];
    float v1 = acc1 * inv + b1[c1];
    v0 = v0 > 0.f ? v0 : expm1f(v0);          // ELU
    v1 = v1 > 0.f ? v1 : expm1f(v1);

    float p0 = v0 * W2[c0 * 2 + 0] + v1 * W2[c1 * 2 + 0];
    float p1 = v0 * W2[c0 * 2 + 1] + v1 * W2[c1 * 2 + 1];
    #pragma unroll
    for (int o = 16; o > 0; o >>= 1) {
        p0 += __shfl_down_sync(FULL, p0, o);
        p1 += __shfl_down_sync(FULL, p1, o);
    }
    if (lane == 0) {
        g_h3[n * 2 + 0] = p0;
        g_h3[n * 2 + 1] = p1;
        g_as2[n] = p0 * as2[0] + p1 * as2[1];
        g_ad2[n] = p0 * ad2[0] + p1 * ad2[1];
    }
}

// ---------------- layer-2 aggregation + output: half-warp per node ------------
__global__ __launch_bounds__(256) void k_agg2(
    float* __restrict__ out, const float* __restrict__ b2) {

    int sub = threadIdx.x & 15;
    int n = blockIdx.x * 16 + (threadIdx.x >> 4);
    if (n >= NN) return;

    float ad = g_ad2[n];
    int start = __ldg(g_offs + n);
    int end = __ldg(g_offs + n + 1);

    float a0 = 0.f, a1 = 0.f, wsum = 0.f;
    for (int i = start + sub; i < end; i += 16) {
        int s = __ldg(g_csr_src + i);
        float w = __expf(lrelu(__ldg(g_as2 + s) + ad));
        float2 hv = *(const float2*)(g_h3 + s * 2);
        a0 += w * hv.x;
        a1 += w * hv.y;
        wsum += w;
    }
    #pragma unroll
    for (int o = 8; o > 0; o >>= 1) {
        a0   += __shfl_down_sync(0xffffffffu, a0, o, 16);
        a1   += __shfl_down_sync(0xffffffffu, a1, o, 16);
        wsum += __shfl_down_sync(0xffffffffu, wsum, o, 16);
    }
    if (sub == 0) {
        float inv = 1.0f / (wsum + 1e-16f);
        out[n * 2 + 0] = a0 * inv + b2[0];
        out[n * 2 + 1] = a1 * inv + b2[1];
    }
}

// ---------------- launch ------------------------------------------------------
extern "C" void kernel_launch(void* const* d_in, const int* in_sizes, int n_in,
                              void* d_out, int out_size) {
    const float* x    = (const float*)d_in[0];
    const int*   ei   = (const int*)  d_in[1];
    const float* W1   = (const float*)d_in[2];
    const float* as1  = (const float*)d_in[3];
    const float* ad1  = (const float*)d_in[4];
    const float* b1   = (const float*)d_in[5];
    const float* W2   = (const float*)d_in[6];
    const float* as2  = (const float*)d_in[7];
    const float* ad2  = (const float*)d_in[8];
    const float* b2   = (const float*)d_in[9];
    float* out = (float*)d_out;

    // One-time host-side resources (host objects only; no device allocation).
    static cudaStream_t s2 = nullptr;
    static cudaEvent_t evFork = nullptr, evJoin = nullptr;
    if (!s2) {
        cudaStreamCreateWithFlags(&s2, cudaStreamNonBlocking);
        cudaEventCreateWithFlags(&evFork, cudaEventDisableTiming);
        cudaEventCreateWithFlags(&evJoin, cudaEventDisableTiming);
        cudaFuncSetAttribute(k_gemm1,
            cudaFuncAttributeMaxDynamicSharedMemorySize, GEMM_SMEM);
    }

    const int T = 256;

    // Fork: CSR build chain (depends only on ei) on s2, concurrent with GEMM.
    cudaEventRecord(evFork, 0);
    cudaStreamWaitEvent(s2, evFork, 0);

    k_gemm1<<<(NN + GN - 1) / GN, 128, GEMM_SMEM>>>(x, W1, as1, ad1);

    k_count<<<(ETOT / 8 + T - 1) / T, T, 0, s2>>>(ei);
    k_scanF<<<NBLK, SCAN_BLK, 0, s2>>>();
    k_scatter<<<(ETOT / 8 + T - 1) / T, T, 0, s2>>>(ei);

    // Join
    cudaEventRecord(evJoin, s2);
    cudaStreamWaitEvent(0, evJoin, 0);

    k_agg1<<<(NN + 7) / 8, T>>>(b1, W2, as2, ad2);
    k_agg2<<<(NN + 15) / 16, T>>>(out, b2);
}